// round 12
// baseline (speedup 1.0000x reference)
#include <cuda_runtime.h>
#include <cuda_fp16.h>
#include <cstdint>

#define MTOT 172032
#define DM   768
#define MT_TILES 1344
#define NT_TILES 6

#define PITCH 80                 // bytes per 32-fp16 row (conflict-free ldmatrix)
#define PLANE (128 * PITCH)      // 10240
#define STGB  (2 * PLANE)        // 20480: A|B
#define NST   5
#define SMEM_OUT (NST * STGB)    // 102400 (covers 67584B fp32 epilogue staging)

// k_h1: K=48, pitch 112
#define HPITCH 112
#define HPL (128 * HPITCH)       // 14336
#define H1_EPI (2 * HPL)         // 28672
#define SMEM_H1 (H1_EPI + 34816) // 63488

// ---------------- global scratch (fp16) ----------------
__device__ __half g_x  [(size_t)MTOT * 64];   // gathered patches, [m][64] (k>=48 zero)
__device__ __half g_x48[(size_t)MTOT * 48];   // gathered patches, [m][48] (for k_h1)
__device__ __half g_h1 [(size_t)MTOT * DM];   // hidden, [m][768]
__device__ __half g_w2 [DM * DM];             // [n][k]
__device__ __half g_cw [DM * 64];             // conv weight, [n][64] (k>=48 zero)
__device__ __half g_cw1[DM * 48];             // (cw^T @ w1)^T, [n][48]

// ---------------- helpers ----------------
__device__ __forceinline__ uint32_t smem_u32(const void* p) {
    uint32_t a;
    asm("{ .reg .u64 t; cvta.to.shared.u64 t, %1; cvt.u32.u64 %0, t; }" : "=r"(a) : "l"(p));
    return a;
}
__device__ __forceinline__ void cp16(uint32_t s, const void* g) {
    asm volatile("cp.async.cg.shared.global [%0], [%1], 16;" ::
                 "r"(s), "l"(__cvta_generic_to_global(g)));
}
#define CP_COMMIT() asm volatile("cp.async.commit_group;" ::: "memory")
template <int N>
__device__ __forceinline__ void cp_wait() {
    asm volatile("cp.async.wait_group %0;" :: "n"(N) : "memory");
}

__device__ __forceinline__ void ldmat4(uint32_t (&r)[4], uint32_t a) {
    asm volatile("ldmatrix.sync.aligned.m8n8.x4.shared.b16 {%0,%1,%2,%3}, [%4];"
                 : "=r"(r[0]), "=r"(r[1]), "=r"(r[2]), "=r"(r[3]) : "r"(a));
}
__device__ __forceinline__ void mma16816(float (&d)[4], const uint32_t* a, uint32_t b0, uint32_t b1) {
    asm volatile("mma.sync.aligned.m16n8k16.row.col.f32.f16.f16.f32 "
                 "{%0,%1,%2,%3},{%4,%5,%6,%7},{%8,%9},{%0,%1,%2,%3};"
                 : "+f"(d[0]), "+f"(d[1]), "+f"(d[2]), "+f"(d[3])
                 : "r"(a[0]), "r"(a[1]), "r"(a[2]), "r"(a[3]), "r"(b0), "r"(b1));
}

// ---- one BK=32 chunk (pitch 80); A plane at stg, B plane at stg+PLANE ----
__device__ __forceinline__ void compute_chunk1(uint32_t stg, int wm, int wn, int lane,
                                               float (&acc)[2][8][4]) {
    uint32_t r16 = (uint32_t)(lane & 15) * PITCH;
    uint32_t khalf = (uint32_t)(lane >> 4) * 16;
#pragma unroll
    for (int k16 = 0; k16 < 2; k16++) {
        uint32_t kc = khalf + (uint32_t)(k16 * 32);
        uint32_t af[2][4];
#pragma unroll
        for (int mf = 0; mf < 2; mf++)
            ldmat4(af[mf], stg + (uint32_t)(wm + mf * 16) * PITCH + r16 + kc);
#pragma unroll
        for (int ng = 0; ng < 4; ng++) {
            uint32_t bf[4];
            ldmat4(bf, stg + PLANE + (uint32_t)(wn + ng * 16) * PITCH + r16 + kc);
#pragma unroll
            for (int mf = 0; mf < 2; mf++)
#pragma unroll
                for (int sub = 0; sub < 2; sub++) {
                    int nf = ng * 2 + sub;
                    uint32_t b0 = sub ? bf[1] : bf[0];
                    uint32_t b1 = sub ? bf[3] : bf[2];
                    mma16816(acc[mf][nf], af[mf], b0, b1);
                }
        }
    }
}

// ---------------- merged prep ----------------
#define NX ((size_t)MTOT * 64)    // 11010048
#define NX48 ((size_t)MTOT * 48)
#define NW (DM * DM)              // 589824
#define NC (DM * 64)              // 49152
__global__ void k_prep(const float* __restrict__ w2, const float* __restrict__ cw,
                       const float* __restrict__ x) {
    size_t gid = (size_t)blockIdx.x * 256 + threadIdx.x;
    if (gid < NX) {
        int m = (int)(gid >> 6), k = (int)(gid & 63);
        int seq = m >> 7, r = m & 127;
        __half v = __float2half(0.f);
        if (k < 48) {
            int t = k >> 4, i = k & 15;
            int pp = (r + t + 127) & 127;
            int j = pp * 8 + i;
            if (j > 1023) j = 1023;
            v = __float2half(x[(size_t)seq * 1024 + j]);
            g_x48[(size_t)m * 48 + k] = v;
        }
        g_x[gid] = v;
        return;
    }
    size_t g2 = gid - NX;
    if (g2 < NW) {
        int k = (int)(g2 / DM), n = (int)(g2 - (size_t)k * DM);
        g_w2[(size_t)n * DM + k] = __float2half(w2[g2]);
        return;
    }
    size_t g3 = g2 - NW;
    if (g3 < NC) {
        int n = (int)(g3 >> 6), k = (int)(g3 & 63);
        float v = 0.f;
        if (k < 48) { int i = k & 15, t = k >> 4; v = cw[n * 48 + i * 3 + t]; }
        g_cw[g3] = __float2half(v);
    }
}

// ---------------- cw1[n][k] = sum_d conv_w[d][map(k)] * w1[d][n] ----------------
__global__ void k_cw1(const float* __restrict__ cw, const float* __restrict__ w1) {
    __shared__ float col[768];
    int k = blockIdx.x;                // 0..47
    int i = k & 15, t = k >> 4;
    for (int d = threadIdx.x; d < 768; d += 128) col[d] = cw[d * 48 + i * 3 + t];
    __syncthreads();
    int n = blockIdx.y * 128 + threadIdx.x;
    float s = 0.f;
#pragma unroll 8
    for (int d = 0; d < 768; d++) s += col[d] * w1[(size_t)d * 768 + n];
    g_cw1[(size_t)n * 48 + k] = __float2half(s);
}

// ---------------- h1 = relu(x48 @ cw1^T + b1): K=48, 2 m-tiles per CTA ----------------
__global__ void __launch_bounds__(256, 2) k_h1(const float* __restrict__ bias) {
    extern __shared__ __align__(128) char smem[];
    uint32_t sb = smem_u32(smem);
    int tid = threadIdx.x, wid = tid >> 5, lane = tid & 31;
    int wm = (wid & 3) * 32, wn = (wid >> 2) * 64;
    int mbase = blockIdx.y * 256, n0 = blockIdx.x * 128;

    // B plane (persists): 128 rows x 48 halfs (6 cp16/row), at HPL
#pragma unroll
    for (int it = 0; it < 3; it++) {
        int idx = tid + it * 256;                  // 0..767
        int row = idx / 6, c = idx - row * 6;
        uint32_t so = HPL + (uint32_t)row * HPITCH + (uint32_t)c * 16;
        cp16(sb + so, g_cw1 + (size_t)(n0 + row) * 48 + c * 8);
    }

    int rin = lane >> 2, colp = (lane & 3) * 2;
#pragma unroll 1
    for (int mi = 0; mi < 2; mi++) {
        int m0 = mbase + mi * 128;
#pragma unroll
        for (int it = 0; it < 3; it++) {
            int idx = tid + it * 256;
            int row = idx / 6, c = idx - row * 6;
            uint32_t so = (uint32_t)row * HPITCH + (uint32_t)c * 16;
            cp16(sb + so, g_x48 + (size_t)(m0 + row) * 48 + c * 8);
        }
        CP_COMMIT();
        cp_wait<0>();
        __syncthreads();

        float acc[2][8][4];
#pragma unroll
        for (int a = 0; a < 2; a++)
#pragma unroll
            for (int b = 0; b < 8; b++)
#pragma unroll
                for (int c = 0; c < 4; c++) acc[a][b][c] = 0.f;

        {
            uint32_t r16 = (uint32_t)(lane & 15) * HPITCH;
            uint32_t khalf = (uint32_t)(lane >> 4) * 16;
#pragma unroll
            for (int k16 = 0; k16 < 3; k16++) {
                uint32_t kc = khalf + (uint32_t)(k16 * 32);
                uint32_t af[2][4];
#pragma unroll
                for (int mf = 0; mf < 2; mf++)
                    ldmat4(af[mf], sb + (uint32_t)(wm + mf * 16) * HPITCH + r16 + kc);
#pragma unroll
                for (int ng = 0; ng < 4; ng++) {
                    uint32_t bf[4];
                    ldmat4(bf, sb + HPL + (uint32_t)(wn + ng * 16) * HPITCH + r16 + kc);
#pragma unroll
                    for (int mf = 0; mf < 2; mf++)
#pragma unroll
                        for (int sub = 0; sub < 2; sub++) {
                            int nf = ng * 2 + sub;
                            uint32_t b0 = sub ? bf[1] : bf[0];
                            uint32_t b1 = sub ? bf[3] : bf[2];
                            mma16816(acc[mf][nf], af[mf], b0, b1);
                        }
                }
            }
        }
        __syncthreads();

        char* smc = smem + H1_EPI;
#pragma unroll
        for (int mf = 0; mf < 2; mf++)
#pragma unroll
            for (int nf = 0; nf < 8; nf++) {
                int cn = wn + nf * 8 + colp;
                float b0 = bias[n0 + cn], b1 = bias[n0 + cn + 1];
#pragma unroll
                for (int half = 0; half < 2; half++) {
                    int rr = wm + mf * 16 + rin + half * 8;
                    __half2 hp;
                    hp.x = __float2half(fmaxf(acc[mf][nf][half * 2] + b0, 0.f));
                    hp.y = __float2half(fmaxf(acc[mf][nf][half * 2 + 1] + b1, 0.f));
                    *(__half2*)(smc + (size_t)rr * 272 + cn * 2) = hp;
                }
            }
        __syncthreads();
        for (int i = tid; i < 2048; i += 256) {
            int r = i >> 4, c = i & 15;
            uint4 vh = *(uint4*)(smc + (size_t)r * 272 + c * 16);
            *(uint4*)(g_h1 + (size_t)(m0 + r) * DM + n0 + c * 8) = vh;
        }
        __syncthreads();
    }
}

// ---------------- out = h1 @ w2^T + x @ cw^T + b2 (fp32), two-sync multistage ----------------
#define NCH_MAIN 24
#define NCH_ALL  26
__global__ void __launch_bounds__(256, 2) k_out(const float* __restrict__ bias,
                                                float* __restrict__ outF) {
    extern __shared__ __align__(128) char smem[];
    uint32_t sb = smem_u32(smem);
    int tid = threadIdx.x, wid = tid >> 5, lane = tid & 31;
    int wm = (wid & 3) * 32, wn = (wid >> 2) * 64;
    int m0 = blockIdx.y * 128, n0 = blockIdx.x * 128;

    // hoisted per-thread loader offsets
    int lrow = tid >> 2, lcol = (tid & 3) * 8;
    uint32_t so0 = (uint32_t)lrow * PITCH + (uint32_t)(tid & 3) * 16;
    uint32_t so1 = so0 + 64 * PITCH;
    const __half* Am = g_h1 + (size_t)(m0 + lrow) * DM + lcol;
    const __half* Bm = g_w2 + (size_t)(n0 + lrow) * DM + lcol;
    const __half* Ar = g_x  + (size_t)(m0 + lrow) * 64 + lcol;
    const __half* Br = g_cw + (size_t)(n0 + lrow) * 64 + lcol;
    const size_t am64 = (size_t)64 * DM, r64 = (size_t)64 * 64;

    auto load_chunk = [&](uint32_t stg, int cn) {
        if (cn < NCH_MAIN) {
            const __half* A = Am + cn * 32;
            const __half* B = Bm + cn * 32;
            cp16(stg + so0, A);
            cp16(stg + so1, A + am64);
            cp16(stg + PLANE + so0, B);
            cp16(stg + PLANE + so1, B + am64);
        } else {
            int rc = cn - NCH_MAIN;
            const __half* A = Ar + rc * 32;
            const __half* B = Br + rc * 32;
            cp16(stg + so0, A);
            cp16(stg + so1, A + r64);
            cp16(stg + PLANE + so0, B);
            cp16(stg + PLANE + so1, B + r64);
        }
    };

    float acc[2][8][4];
#pragma unroll
    for (int a = 0; a < 2; a++)
#pragma unroll
        for (int b = 0; b < 8; b++)
#pragma unroll
            for (int c = 0; c < 4; c++) acc[a][b][c] = 0.f;

    // prologue: fill all NST stages
#pragma unroll
    for (int s = 0; s < NST; s++) {
        load_chunk(sb + (uint32_t)s * STGB, s);
        CP_COMMIT();
    }

    // two-sync mainloop (R10 schedule)
#pragma unroll 1
    for (int c = 0; c < NCH_ALL; c++) {
        cp_wait<NST - 1>();
        __syncthreads();
        uint32_t stg = sb + (uint32_t)(c % NST) * STGB;
        compute_chunk1(stg, wm, wn, lane, acc);
        __syncthreads();
        int cn = c + NST;
        if (cn < NCH_ALL) load_chunk(stg, cn);
        CP_COMMIT();
    }

    // epilogue: bias, fp32 smem stage (pitch 132 floats), coalesced out
    int rin = lane >> 2, colp = (lane & 3) * 2;
    float* smf = (float*)smem;
#pragma unroll
    for (int mf = 0; mf < 2; mf++)
#pragma unroll
        for (int nf = 0; nf < 8; nf++) {
            int cn = wn + nf * 8 + colp;
            float b0 = bias[n0 + cn], b1 = bias[n0 + cn + 1];
#pragma unroll
            for (int half = 0; half < 2; half++) {
                int rr = wm + mf * 16 + rin + half * 8;
                float2 v;
                v.x = acc[mf][nf][half * 2] + b0;
                v.y = acc[mf][nf][half * 2 + 1] + b1;
                *(float2*)(smf + (size_t)rr * 132 + cn) = v;
            }
        }
    __syncthreads();
    for (int i = tid; i < 4096; i += 256) {
        int r = i >> 5, c = i & 31;
        float4 v0 = *(float4*)(smf + (size_t)r * 132 + c * 4);
        *(float4*)(outF + (size_t)(m0 + r) * DM + n0 + c * 4) = v0;
    }
}

// ---------------- launcher ----------------
extern "C" void kernel_launch(void* const* d_in, const int* in_sizes, int n_in,
                              void* d_out, int out_size) {
    (void)in_sizes; (void)n_in; (void)out_size;
    const float* x      = (const float*)d_in[0];
    const float* conv_w = (const float*)d_in[1];
    const float* w1     = (const float*)d_in[2];
    const float* b1     = (const float*)d_in[3];
    const float* w2     = (const float*)d_in[4];
    const float* b2     = (const float*)d_in[5];
    float* out = (float*)d_out;

    cudaFuncSetAttribute((const void*)k_h1,
                         cudaFuncAttributeMaxDynamicSharedMemorySize, SMEM_H1);
    cudaFuncSetAttribute((const void*)k_out,
                         cudaFuncAttributeMaxDynamicSharedMemorySize, SMEM_OUT);

    size_t total = NX + (size_t)NW + NC;
    k_prep<<<(unsigned)((total + 255) / 256), 256>>>(w2, conv_w, x);
    {
        dim3 g(48, 6);
        k_cw1<<<g, 128>>>(conv_w, w1);
    }
    {
        dim3 g(NT_TILES, MT_TILES / 2);
        k_h1<<<g, 256, SMEM_H1>>>(b1);
    }
    {
        dim3 g(NT_TILES, MT_TILES);
        k_out<<<g, 256, SMEM_OUT>>>(b2, out);
    }
}

// round 13
// speedup vs baseline: 1.0912x; 1.0912x over previous
#include <cuda_runtime.h>
#include <cuda_fp16.h>
#include <cstdint>

#define MTOT 172032
#define DM   768
#define MT_TILES 1344
#define NT_TILES 6

#define PITCH 80                 // bytes per 32-fp16 row (conflict-free ldmatrix)
#define PLANE (128 * PITCH)      // 10240
#define STGB  (2 * PLANE)        // 20480: A|B
#define NST   4
#define SMEM_OUT (NST * STGB)    // 81920 (covers 67584B fp32 epilogue staging)

// k_h1: K=48, pitch 112
#define HPITCH 112
#define HPL (128 * HPITCH)       // 14336
#define H1_EPI (2 * HPL)         // 28672
#define SMEM_H1 (H1_EPI + 34816) // 63488

// ---------------- global scratch (fp16) ----------------
__device__ __half g_x  [(size_t)MTOT * 64];   // gathered patches, [m][64] (k>=48 zero)
__device__ __half g_x48[(size_t)MTOT * 48];   // gathered patches, [m][48] (for k_h1)
__device__ __half g_h1 [(size_t)MTOT * DM];   // hidden, [m][768]
__device__ __half g_w2 [DM * DM];             // [n][k]
__device__ __half g_cw [DM * 64];             // conv weight, [n][64] (k>=48 zero)
__device__ __half g_cw1[DM * 48];             // (cw^T @ w1)^T, [n][48]

// ---------------- helpers ----------------
__device__ __forceinline__ uint32_t smem_u32(const void* p) {
    uint32_t a;
    asm("{ .reg .u64 t; cvta.to.shared.u64 t, %1; cvt.u32.u64 %0, t; }" : "=r"(a) : "l"(p));
    return a;
}
__device__ __forceinline__ void cp16(uint32_t s, const void* g) {
    asm volatile("cp.async.cg.shared.global [%0], [%1], 16;" ::
                 "r"(s), "l"(__cvta_generic_to_global(g)));
}
#define CP_COMMIT() asm volatile("cp.async.commit_group;" ::: "memory")
template <int N>
__device__ __forceinline__ void cp_wait() {
    asm volatile("cp.async.wait_group %0;" :: "n"(N) : "memory");
}

__device__ __forceinline__ void ldmat4(uint32_t (&r)[4], uint32_t a) {
    asm volatile("ldmatrix.sync.aligned.m8n8.x4.shared.b16 {%0,%1,%2,%3}, [%4];"
                 : "=r"(r[0]), "=r"(r[1]), "=r"(r[2]), "=r"(r[3]) : "r"(a));
}
__device__ __forceinline__ void mma16816(float (&d)[4], const uint32_t* a, uint32_t b0, uint32_t b1) {
    asm volatile("mma.sync.aligned.m16n8k16.row.col.f32.f16.f16.f32 "
                 "{%0,%1,%2,%3},{%4,%5,%6,%7},{%8,%9},{%0,%1,%2,%3};"
                 : "+f"(d[0]), "+f"(d[1]), "+f"(d[2]), "+f"(d[3])
                 : "r"(a[0]), "r"(a[1]), "r"(a[2]), "r"(a[3]), "r"(b0), "r"(b1));
}

// ---- one BK=32 chunk (pitch 80); A plane at stg, B plane at stg+PLANE ----
__device__ __forceinline__ void compute_chunk1(uint32_t stg, int wm, int wn, int lane,
                                               float (&acc)[2][8][4]) {
    uint32_t r16 = (uint32_t)(lane & 15) * PITCH;
    uint32_t khalf = (uint32_t)(lane >> 4) * 16;
#pragma unroll
    for (int k16 = 0; k16 < 2; k16++) {
        uint32_t kc = khalf + (uint32_t)(k16 * 32);
        uint32_t af[2][4];
#pragma unroll
        for (int mf = 0; mf < 2; mf++)
            ldmat4(af[mf], stg + (uint32_t)(wm + mf * 16) * PITCH + r16 + kc);
#pragma unroll
        for (int ng = 0; ng < 4; ng++) {
            uint32_t bf[4];
            ldmat4(bf, stg + PLANE + (uint32_t)(wn + ng * 16) * PITCH + r16 + kc);
#pragma unroll
            for (int mf = 0; mf < 2; mf++)
#pragma unroll
                for (int sub = 0; sub < 2; sub++) {
                    int nf = ng * 2 + sub;
                    uint32_t b0 = sub ? bf[1] : bf[0];
                    uint32_t b1 = sub ? bf[3] : bf[2];
                    mma16816(acc[mf][nf], af[mf], b0, b1);
                }
        }
    }
}

// ---- compile-time-stride stage loader (R10) ----
template <int AS, int BS>
__device__ __forceinline__ void load_stage_t(uint32_t stg,
                                             const __half* __restrict__ A,
                                             const __half* __restrict__ B,
                                             int tid) {
#pragma unroll
    for (int it = 0; it < 2; it++) {
        int idx = tid + it * 256;                  // 0..511
        int row = idx >> 2, c = idx & 3;
        uint32_t so = (uint32_t)row * PITCH + (uint32_t)c * 16;
        cp16(stg + so, A + (size_t)row * AS + c * 8);
        cp16(stg + PLANE + so, B + (size_t)row * BS + c * 8);
    }
}

// ---------------- merged prep ----------------
#define NX ((size_t)MTOT * 64)    // 11010048
#define NW (DM * DM)              // 589824
#define NC (DM * 64)              // 49152
__global__ void k_prep(const float* __restrict__ w2, const float* __restrict__ cw,
                       const float* __restrict__ x) {
    size_t gid = (size_t)blockIdx.x * 256 + threadIdx.x;
    if (gid < NX) {
        int m = (int)(gid >> 6), k = (int)(gid & 63);
        int seq = m >> 7, r = m & 127;
        __half v = __float2half(0.f);
        if (k < 48) {
            int t = k >> 4, i = k & 15;
            int pp = (r + t + 127) & 127;
            int j = pp * 8 + i;
            if (j > 1023) j = 1023;
            v = __float2half(x[(size_t)seq * 1024 + j]);
            g_x48[(size_t)m * 48 + k] = v;
        }
        g_x[gid] = v;
        return;
    }
    size_t g2 = gid - NX;
    if (g2 < NW) {
        int k = (int)(g2 / DM), n = (int)(g2 - (size_t)k * DM);
        g_w2[(size_t)n * DM + k] = __float2half(w2[g2]);
        return;
    }
    size_t g3 = g2 - NW;
    if (g3 < NC) {
        int n = (int)(g3 >> 6), k = (int)(g3 & 63);
        float v = 0.f;
        if (k < 48) { int i = k & 15, t = k >> 4; v = cw[n * 48 + i * 3 + t]; }
        g_cw[g3] = __float2half(v);
    }
}

// ---------------- cw1[n][k] = sum_d conv_w[d][map(k)] * w1[d][n] ----------------
__global__ void k_cw1(const float* __restrict__ cw, const float* __restrict__ w1) {
    __shared__ float col[768];
    int k = blockIdx.x;                // 0..47
    int i = k & 15, t = k >> 4;
    for (int d = threadIdx.x; d < 768; d += 128) col[d] = cw[d * 48 + i * 3 + t];
    __syncthreads();
    int n = blockIdx.y * 128 + threadIdx.x;
    float s = 0.f;
#pragma unroll 8
    for (int d = 0; d < 768; d++) s += col[d] * w1[(size_t)d * 768 + n];
    g_cw1[(size_t)n * 48 + k] = __float2half(s);
}

// ---------------- h1 = relu(x48 @ cw1^T + b1): K=48, 2 m-tiles per CTA ----------------
__global__ void __launch_bounds__(256, 2) k_h1(const float* __restrict__ bias) {
    extern __shared__ __align__(128) char smem[];
    uint32_t sb = smem_u32(smem);
    int tid = threadIdx.x, wid = tid >> 5, lane = tid & 31;
    int wm = (wid & 3) * 32, wn = (wid >> 2) * 64;
    int mbase = blockIdx.y * 256, n0 = blockIdx.x * 128;

    // B plane (persists): 128 rows x 48 halfs (6 cp16/row), at HPL
#pragma unroll
    for (int it = 0; it < 3; it++) {
        int idx = tid + it * 256;                  // 0..767
        int row = idx / 6, c = idx - row * 6;
        uint32_t so = HPL + (uint32_t)row * HPITCH + (uint32_t)c * 16;
        cp16(sb + so, g_cw1 + (size_t)(n0 + row) * 48 + c * 8);
    }

    int rin = lane >> 2, colp = (lane & 3) * 2;
#pragma unroll 1
    for (int mi = 0; mi < 2; mi++) {
        int m0 = mbase + mi * 128;
#pragma unroll
        for (int it = 0; it < 3; it++) {
            int idx = tid + it * 256;
            int row = idx / 6, c = idx - row * 6;
            uint32_t so = (uint32_t)row * HPITCH + (uint32_t)c * 16;
            cp16(sb + so, g_x48 + (size_t)(m0 + row) * 48 + c * 8);
        }
        CP_COMMIT();
        cp_wait<0>();
        __syncthreads();

        float acc[2][8][4];
#pragma unroll
        for (int a = 0; a < 2; a++)
#pragma unroll
            for (int b = 0; b < 8; b++)
#pragma unroll
                for (int c = 0; c < 4; c++) acc[a][b][c] = 0.f;

        {
            uint32_t r16 = (uint32_t)(lane & 15) * HPITCH;
            uint32_t khalf = (uint32_t)(lane >> 4) * 16;
#pragma unroll
            for (int k16 = 0; k16 < 3; k16++) {
                uint32_t kc = khalf + (uint32_t)(k16 * 32);
                uint32_t af[2][4];
#pragma unroll
                for (int mf = 0; mf < 2; mf++)
                    ldmat4(af[mf], sb + (uint32_t)(wm + mf * 16) * HPITCH + r16 + kc);
#pragma unroll
                for (int ng = 0; ng < 4; ng++) {
                    uint32_t bf[4];
                    ldmat4(bf, sb + HPL + (uint32_t)(wn + ng * 16) * HPITCH + r16 + kc);
#pragma unroll
                    for (int mf = 0; mf < 2; mf++)
#pragma unroll
                        for (int sub = 0; sub < 2; sub++) {
                            int nf = ng * 2 + sub;
                            uint32_t b0 = sub ? bf[1] : bf[0];
                            uint32_t b1 = sub ? bf[3] : bf[2];
                            mma16816(acc[mf][nf], af[mf], b0, b1);
                        }
                }
            }
        }
        __syncthreads();

        char* smc = smem + H1_EPI;
#pragma unroll
        for (int mf = 0; mf < 2; mf++)
#pragma unroll
            for (int nf = 0; nf < 8; nf++) {
                int cn = wn + nf * 8 + colp;
                float b0 = bias[n0 + cn], b1 = bias[n0 + cn + 1];
#pragma unroll
                for (int half = 0; half < 2; half++) {
                    int rr = wm + mf * 16 + rin + half * 8;
                    __half2 hp;
                    hp.x = __float2half(fmaxf(acc[mf][nf][half * 2] + b0, 0.f));
                    hp.y = __float2half(fmaxf(acc[mf][nf][half * 2 + 1] + b1, 0.f));
                    *(__half2*)(smc + (size_t)rr * 272 + cn * 2) = hp;
                }
            }
        __syncthreads();
        for (int i = tid; i < 2048; i += 256) {
            int r = i >> 4, c = i & 15;
            uint4 vh = *(uint4*)(smc + (size_t)r * 272 + c * 16);
            *(uint4*)(g_h1 + (size_t)(m0 + r) * DM + n0 + c * 8) = vh;
        }
        __syncthreads();
    }
}

// ---------------- out = h1 @ w2^T + x @ cw^T + b2 (fp32) — R10 schedule verbatim ----------------
#define NCH_MAIN 24
#define NCH_ALL  26
__global__ void __launch_bounds__(256, 2) k_out(const float* __restrict__ bias,
                                                float* __restrict__ outF) {
    extern __shared__ __align__(128) char smem[];
    uint32_t sb = smem_u32(smem);
    int tid = threadIdx.x, wid = tid >> 5, lane = tid & 31;
    int wm = (wid & 3) * 32, wn = (wid >> 2) * 64;
    int m0 = blockIdx.y * 128, n0 = blockIdx.x * 128;

    const __half* Abase = g_h1 + (size_t)m0 * DM;
    const __half* Bbase = g_w2 + (size_t)n0 * DM;
    const __half* Ares  = g_x  + (size_t)m0 * 64;
    const __half* Bres  = g_cw + (size_t)n0 * 64;

    float acc[2][8][4];
#pragma unroll
    for (int a = 0; a < 2; a++)
#pragma unroll
        for (int b = 0; b < 8; b++)
#pragma unroll
            for (int c = 0; c < 4; c++) acc[a][b][c] = 0.f;

#pragma unroll
    for (int s = 0; s < NST; s++) {
        load_stage_t<DM, DM>(sb + (uint32_t)s * STGB, Abase + s * 32, Bbase + s * 32, tid);
        CP_COMMIT();
    }

#pragma unroll 1
    for (int c = 0; c < NCH_ALL; c++) {
        cp_wait<NST - 1>();
        __syncthreads();
        uint32_t stg = sb + (uint32_t)(c & 3) * STGB;
        compute_chunk1(stg, wm, wn, lane, acc);
        __syncthreads();
        int cn = c + NST;
        if (cn < NCH_MAIN) {
            load_stage_t<DM, DM>(stg, Abase + cn * 32, Bbase + cn * 32, tid);
        } else if (cn < NCH_ALL) {
            int rc = cn - NCH_MAIN;
            load_stage_t<64, 64>(stg, Ares + rc * 32, Bres + rc * 32, tid);
        }
        CP_COMMIT();
    }

    // epilogue: bias, fp32 smem stage (pitch 132 floats), coalesced out
    int rin = lane >> 2, colp = (lane & 3) * 2;
    float* smf = (float*)smem;
#pragma unroll
    for (int mf = 0; mf < 2; mf++)
#pragma unroll
        for (int nf = 0; nf < 8; nf++) {
            int cn = wn + nf * 8 + colp;
            float b0 = bias[n0 + cn], b1 = bias[n0 + cn + 1];
#pragma unroll
            for (int half = 0; half < 2; half++) {
                int rr = wm + mf * 16 + rin + half * 8;
                float2 v;
                v.x = acc[mf][nf][half * 2] + b0;
                v.y = acc[mf][nf][half * 2 + 1] + b1;
                *(float2*)(smf + (size_t)rr * 132 + cn) = v;
            }
        }
    __syncthreads();
    for (int i = tid; i < 4096; i += 256) {
        int r = i >> 5, c = i & 31;
        float4 v0 = *(float4*)(smf + (size_t)r * 132 + c * 4);
        *(float4*)(outF + (size_t)(m0 + r) * DM + n0 + c * 4) = v0;
    }
}

// ---------------- launcher ----------------
extern "C" void kernel_launch(void* const* d_in, const int* in_sizes, int n_in,
                              void* d_out, int out_size) {
    (void)in_sizes; (void)n_in; (void)out_size;
    const float* x      = (const float*)d_in[0];
    const float* conv_w = (const float*)d_in[1];
    const float* w1     = (const float*)d_in[2];
    const float* b1     = (const float*)d_in[3];
    const float* w2     = (const float*)d_in[4];
    const float* b2     = (const float*)d_in[5];
    float* out = (float*)d_out;

    cudaFuncSetAttribute((const void*)k_h1,
                         cudaFuncAttributeMaxDynamicSharedMemorySize, SMEM_H1);
    cudaFuncSetAttribute((const void*)k_out,
                         cudaFuncAttributeMaxDynamicSharedMemorySize, SMEM_OUT);

    size_t total = NX + (size_t)NW + NC;
    k_prep<<<(unsigned)((total + 255) / 256), 256>>>(w2, conv_w, x);
    {
        dim3 g(48, 6);
        k_cw1<<<g, 128>>>(conv_w, w1);
    }
    {
        dim3 g(NT_TILES, MT_TILES / 2);
        k_h1<<<g, 256, SMEM_H1>>>(b1);
    }
    {
        dim3 g(NT_TILES, MT_TILES);
        k_out<<<g, 256, SMEM_OUT>>>(b2, out);
    }
}